// round 3
// baseline (speedup 1.0000x reference)
#include <cuda_runtime.h>
#include <cstdint>

#define BB 16
#define DD 512
#define TT 2048
#define SS 2048      // padded s dimension (valid s < 2047)
#define SVALID 2047

// ---------------- scratch (static __device__, no runtime allocation) ---------
__device__ float g_Qt[(size_t)BB * DD * SS];     // q-tilde, layout [b][d][s] (s contiguous)
__device__ float g_gpart[(size_t)BB * 16 * SS];  // partial g0 per t-tile: [b][tb][s]
__device__ float g_g0[(size_t)BB * SS];          // g0[b][s]
__device__ float g_y[BB * DD];                   // y0[b][d]
__device__ float g_r[BB * DD];                   // rowsum xs over s<2047
__device__ float g_wsum;                         // sum of W_out[-1]

// ---------------- K0: Wsum = sum_t W_out[T-1][t] -----------------------------
__global__ void k0_wsum(const float* __restrict__ W_out) {
    __shared__ float sm[256];
    const float* w = W_out + (size_t)(TT - 1) * TT;
    float acc = 0.f;
    for (int t = threadIdx.x; t < TT; t += 256) acc += w[t];
    sm[threadIdx.x] = acc;
    __syncthreads();
    for (int st = 128; st > 0; st >>= 1) {
        if (threadIdx.x < st) sm[threadIdx.x] += sm[threadIdx.x + st];
        __syncthreads();
    }
    if (threadIdx.x == 0) g_wsum = sm[0];
}

// ---------------- K1: Qt[b][d][s] = sign(d) * sum_k xs[b][k][s] * W_KQ[k][d] -
// 128x128x16 tile, 256 threads, 8x8 microtile. grid = (s-tiles=16, d-tiles=4, b=16)
__global__ __launch_bounds__(256) void k1_qt(const float* __restrict__ xs,
                                             const float* __restrict__ W_KQ) {
    __shared__ float As[16][128];  // [k][s]  (natural layout: xs is s-contiguous)
    __shared__ float Bs[16][128];  // [k][d]

    const int b  = blockIdx.z;
    const int s0 = blockIdx.x * 128;
    const int d0 = blockIdx.y * 128;
    const int tid = threadIdx.x;
    const int tx = tid & 15, ty = tid >> 4;
    const float sign = (blockIdx.y < 2) ? 1.f : -1.f;  // head 0 rows: d<256

    const float* xb = xs + (size_t)b * DD * TT;

    float cc[8][8];  // cc[j][i]: j over d (tx), i over s (ty); i contiguous for f4 stores
#pragma unroll
    for (int j = 0; j < 8; j++)
#pragma unroll
        for (int i = 0; i < 8; i++) cc[j][i] = 0.f;

    const int lk  = tid >> 5;   // 0..7, +8 for second row
    const int ls4 = tid & 31;   // float4 column

    for (int kb = 0; kb < DD; kb += 16) {
        __syncthreads();
#pragma unroll
        for (int r = 0; r < 2; r++) {
            const int k = lk + r * 8;
            *(float4*)&As[k][ls4 * 4] =
                *(const float4*)(xb + (size_t)(kb + k) * TT + s0 + ls4 * 4);
            *(float4*)&Bs[k][ls4 * 4] =
                *(const float4*)(W_KQ + (size_t)(kb + k) * DD + d0 + ls4 * 4);
        }
        __syncthreads();
#pragma unroll
        for (int k = 0; k < 16; k++) {
            float a[8], bv[8];
            *(float4*)&a[0]  = *(const float4*)&As[k][ty * 8];
            *(float4*)&a[4]  = *(const float4*)&As[k][ty * 8 + 4];
            *(float4*)&bv[0] = *(const float4*)&Bs[k][tx * 8];
            *(float4*)&bv[4] = *(const float4*)&Bs[k][tx * 8 + 4];
#pragma unroll
            for (int j = 0; j < 8; j++)
#pragma unroll
                for (int i = 0; i < 8; i++) cc[j][i] += bv[j] * a[i];
        }
    }

    float* q = g_Qt + (size_t)b * DD * SS;
#pragma unroll
    for (int j = 0; j < 8; j++) {
        const int d = d0 + tx * 8 + j;
        float* row = q + (size_t)d * SS + s0 + ty * 8;
#pragma unroll
        for (int i = 0; i < 8; i++) cc[j][i] *= sign;
        *(float4*)&row[0] = *(float4*)&cc[j][0];
        *(float4*)&row[4] = *(float4*)&cc[j][4];
    }
}

// ---------------- K2: Delta GEMM + fused sigmoid/weighted reduce -------------
// Delta[s,t] = sum_d Qt[b][d][s] * xs[b][d][t]; gpart[b][tb][s] += w[t]*sigmoid(Delta)
// grid = (s-tiles=16, t-tiles=16, b=16)
__global__ __launch_bounds__(256) void k2_attn(const float* __restrict__ xs,
                                               const float* __restrict__ W_out) {
    __shared__ float As[16][128];   // [k][s] from Qt (s contiguous -> natural)
    __shared__ float Bs[16][128];   // [k][t] from xs (t contiguous -> natural)
    __shared__ float red[16][132];  // tx-partials per s-row (padded)

    const int b  = blockIdx.z;
    const int s0 = blockIdx.x * 128;
    const int t0 = blockIdx.y * 128;
    const int tid = threadIdx.x;
    const int tx = tid & 15, ty = tid >> 4;

    const float* qb = g_Qt + (size_t)b * DD * SS;
    const float* xb = xs + (size_t)b * DD * TT;

    float cc[8][8];  // cc[j][i]: j over t, i over s
#pragma unroll
    for (int j = 0; j < 8; j++)
#pragma unroll
        for (int i = 0; i < 8; i++) cc[j][i] = 0.f;

    const int lk  = tid >> 5;
    const int ls4 = tid & 31;

    for (int kb = 0; kb < DD; kb += 16) {
        __syncthreads();
#pragma unroll
        for (int r = 0; r < 2; r++) {
            const int k = lk + r * 8;
            *(float4*)&As[k][ls4 * 4] =
                *(const float4*)(qb + (size_t)(kb + k) * SS + s0 + ls4 * 4);
            *(float4*)&Bs[k][ls4 * 4] =
                *(const float4*)(xb + (size_t)(kb + k) * TT + t0 + ls4 * 4);
        }
        __syncthreads();
#pragma unroll
        for (int k = 0; k < 16; k++) {
            float a[8], bv[8];
            *(float4*)&a[0]  = *(const float4*)&As[k][ty * 8];
            *(float4*)&a[4]  = *(const float4*)&As[k][ty * 8 + 4];
            *(float4*)&bv[0] = *(const float4*)&Bs[k][tx * 8];
            *(float4*)&bv[4] = *(const float4*)&Bs[k][tx * 8 + 4];
#pragma unroll
            for (int j = 0; j < 8; j++)
#pragma unroll
                for (int i = 0; i < 8; i++) cc[j][i] += bv[j] * a[i];
        }
    }

    // Epilogue: per s-row, sum over this thread's 8 t-columns of w[t]*sigmoid(delta)
    const float* wrow = W_out + (size_t)(TT - 1) * TT + t0 + tx * 8;
    float w[8];
#pragma unroll
    for (int j = 0; j < 8; j++) w[j] = wrow[j];

#pragma unroll
    for (int i = 0; i < 8; i++) {
        float acc = 0.f;
#pragma unroll
        for (int j = 0; j < 8; j++) {
            const float sg = 1.f / (1.f + __expf(-cc[j][i]));
            acc += w[j] * sg;
        }
        red[tx][ty * 8 + i] = acc;
    }
    __syncthreads();
    if (tid < 128) {
        float acc = 0.f;
#pragma unroll
        for (int c = 0; c < 16; c++) acc += red[c][tid];
        g_gpart[((size_t)b * 16 + blockIdx.y) * SS + s0 + tid] = acc;
    }
}

// ---------------- K3: g0[b][s] = sum_tb gpart ------------------------------
__global__ void k3_g0() {
    const int idx = blockIdx.x * 256 + threadIdx.x;  // over BB*SS
    const int b = idx >> 11;
    const int s = idx & (SS - 1);
    const float* p = g_gpart + (size_t)b * 16 * SS + s;
    float acc = 0.f;
#pragma unroll
    for (int tb = 0; tb < 16; tb++) acc += p[(size_t)tb * SS];
    g_g0[idx] = acc;
}

// ---------------- K4: y0[b][d] = sum_{s<2047} xs*g0 ; r = rowsum(xs) --------
__global__ void k4_y(const float* __restrict__ xs) {
    const int d = blockIdx.x;
    const int b = blockIdx.y;
    const float* xr = xs + ((size_t)b * DD + d) * TT;
    const float* g = g_g0 + (size_t)b * SS;
    float ay = 0.f, ar = 0.f;
    for (int s = threadIdx.x; s < SVALID; s += 128) {
        const float x = xr[s];
        ay += x * g[s];
        ar += x;
    }
    __shared__ float sy[128], sr[128];
    sy[threadIdx.x] = ay;
    sr[threadIdx.x] = ar;
    __syncthreads();
    for (int st = 64; st > 0; st >>= 1) {
        if (threadIdx.x < st) {
            sy[threadIdx.x] += sy[threadIdx.x + st];
            sr[threadIdx.x] += sr[threadIdx.x + st];
        }
        __syncthreads();
    }
    if (threadIdx.x == 0) {
        g_y[b * DD + d] = sy[0];
        g_r[b * DD + d] = sr[0];
    }
}

// ---------------- K5: out[b][i] = sum_d W_PV[i][d] * z_{h(i)}[d] ------------
__global__ __launch_bounds__(512) void k5_out(const float* __restrict__ W_PV,
                                              float* __restrict__ out) {
    const int b = blockIdx.x;
    __shared__ float z0[DD], z1[DD];
    const float ws = g_wsum;
    {
        const int d = threadIdx.x;  // 512 threads, DD = 512
        const float yv = g_y[b * DD + d];
        const float rv = g_r[b * DD + d];
        z0[d] = yv;             // head 0
        z1[d] = ws * rv - yv;   // head 1: (Wsum - g0) path
    }
    __syncthreads();
    const int warp = threadIdx.x >> 5, lane = threadIdx.x & 31;
    for (int ii = 0; ii < 32; ii++) {
        const int i = warp * 32 + ii;
        const float* z = (i < 256) ? z0 : z1;
        const float* wp = W_PV + (size_t)i * DD;
        float acc = 0.f;
#pragma unroll
        for (int c = 0; c < 16; c++) {
            const int d = lane + c * 32;
            acc += wp[d] * z[d];
        }
#pragma unroll
        for (int off = 16; off > 0; off >>= 1)
            acc += __shfl_down_sync(0xffffffffu, acc, off);
        if (lane == 0) out[b * DD + i] = acc;
    }
}

// ---------------- launch -----------------------------------------------------
extern "C" void kernel_launch(void* const* d_in, const int* in_sizes, int n_in,
                              void* d_out, int out_size) {
    const float* xs    = (const float*)d_in[0];
    const float* W_KQ  = (const float*)d_in[1];
    const float* W_PV  = (const float*)d_in[2];
    const float* W_out = (const float*)d_in[3];
    float* out = (float*)d_out;

    k0_wsum<<<1, 256>>>(W_out);
    k1_qt<<<dim3(16, 4, BB), 256>>>(xs, W_KQ);
    k2_attn<<<dim3(16, 16, BB), 256>>>(xs, W_out);
    k3_g0<<<(BB * SS) / 256, 256>>>();
    k4_y<<<dim3(DD, BB), 128>>>(xs);
    k5_out<<<BB, 512>>>(W_PV, out);
}

// round 5
// speedup vs baseline: 2.3349x; 2.3349x over previous
#include <cuda_runtime.h>
#include <cstdint>

#define BB 16
#define DD 512
#define TT 2048
#define SS 2048      // padded s dimension (valid s < 2047)
#define SVALID 2047
#define LDA 136      // smem row stride (floats): 8-bank skew per k-row -> conflict-free frags

// ---------------- scratch (static __device__, no runtime allocation) ---------
__device__ float g_Xt[(size_t)BB * DD * TT];     // tf32-rounded xs
__device__ float g_Wkq[DD * DD];                 // tf32-rounded W_KQ
__device__ float g_Qt[(size_t)BB * DD * SS];     // q-tilde (tf32-rounded), [b][d][s]
__device__ float g_gpart[(size_t)BB * 16 * SS];  // partial g0 per t-tile
__device__ float g_g0[(size_t)BB * SS];
__device__ float g_y[BB * DD];
__device__ float g_r[BB * DD];
__device__ float g_wsum;

// ---------------- helpers ----------------------------------------------------
__device__ __forceinline__ float to_tf32(float x) {
    uint32_t u;
    asm("cvt.rna.tf32.f32 %0, %1;" : "=r"(u) : "f"(x));
    return __uint_as_float(u);
}

__device__ __forceinline__ void mma_tf32(float* c, const uint32_t* a, const uint32_t* b) {
    asm volatile(
        "mma.sync.aligned.m16n8k8.row.col.f32.tf32.tf32.f32 "
        "{%0,%1,%2,%3}, {%4,%5,%6,%7}, {%8,%9}, {%0,%1,%2,%3};"
        : "+f"(c[0]), "+f"(c[1]), "+f"(c[2]), "+f"(c[3])
        : "r"(a[0]), "r"(a[1]), "r"(a[2]), "r"(a[3]), "r"(b[0]), "r"(b[1]));
}

__device__ __forceinline__ float sigmoidf_fast(float x) {
    return 1.f / (1.f + __expf(-x));
}

// ---------------- K0: Wsum ----------------------------------------------------
__global__ void k0_wsum(const float* __restrict__ W_out) {
    __shared__ float sm[256];
    const float* w = W_out + (size_t)(TT - 1) * TT;
    float acc = 0.f;
    for (int t = threadIdx.x; t < TT; t += 256) acc += w[t];
    sm[threadIdx.x] = acc;
    __syncthreads();
    for (int st = 128; st > 0; st >>= 1) {
        if (threadIdx.x < st) sm[threadIdx.x] += sm[threadIdx.x + st];
        __syncthreads();
    }
    if (threadIdx.x == 0) g_wsum = sm[0];
}

// ---------------- pre-pass: round xs, W_KQ to tf32 ---------------------------
__global__ void k_cvt_xs(const float* __restrict__ xs) {
    const size_t i = (size_t)blockIdx.x * 256 + threadIdx.x;  // float4 index
    float4 v = ((const float4*)xs)[i];
    v.x = to_tf32(v.x); v.y = to_tf32(v.y); v.z = to_tf32(v.z); v.w = to_tf32(v.w);
    ((float4*)g_Xt)[i] = v;
}
__global__ void k_cvt_w(const float* __restrict__ w) {
    const size_t i = (size_t)blockIdx.x * 256 + threadIdx.x;
    float4 v = ((const float4*)w)[i];
    v.x = to_tf32(v.x); v.y = to_tf32(v.y); v.z = to_tf32(v.z); v.w = to_tf32(v.w);
    ((float4*)g_Wkq)[i] = v;
}

// ---------------- K1: Qt (tf32 tensor-core GEMM) -----------------------------
// Qt[b][d][s] = sign(d) * sum_k Xt[b][k][s] * Wkq[k][d]
// Block tile 128(s) x 128(d), K=512, BK=16. 8 warps: 2(m) x 4(n), warp tile 64x32.
__global__ __launch_bounds__(256) void k1_qt(const float* __restrict__ dummy) {
    __shared__ float As[16][LDA];  // [k][s]
    __shared__ float Bs[16][LDA];  // [k][d]

    const int b  = blockIdx.z;
    const int s0 = blockIdx.x * 128;
    const int d0 = blockIdx.y * 128;
    const int tid = threadIdx.x;
    const int warp = tid >> 5, lane = tid & 31;
    const int wm = warp & 1;        // 64-row slab
    const int wn = warp >> 1;       // 32-col slab
    const int g = lane >> 2, q = lane & 3;
    const float sign = (blockIdx.y < 2) ? 1.f : -1.f;

    const float* xb = g_Xt + (size_t)b * DD * TT;

    float c[4][4][4];
#pragma unroll
    for (int mf = 0; mf < 4; mf++)
#pragma unroll
        for (int nf = 0; nf < 4; nf++)
#pragma unroll
            for (int r = 0; r < 4; r++) c[mf][nf][r] = 0.f;

    const int lk  = tid >> 5;
    const int ls4 = tid & 31;

    for (int kb = 0; kb < DD; kb += 16) {
        __syncthreads();
#pragma unroll
        for (int r = 0; r < 2; r++) {
            const int k = lk + r * 8;
            *(float4*)&As[k][ls4 * 4] =
                *(const float4*)(xb + (size_t)(kb + k) * TT + s0 + ls4 * 4);
            *(float4*)&Bs[k][ls4 * 4] =
                *(const float4*)(g_Wkq + (size_t)(kb + k) * DD + d0 + ls4 * 4);
        }
        __syncthreads();
#pragma unroll
        for (int kc = 0; kc < 16; kc += 8) {
            uint32_t a[4][4], bv[4][2];
#pragma unroll
            for (int mf = 0; mf < 4; mf++) {
                const int row = wm * 64 + mf * 16 + g;
                a[mf][0] = __float_as_uint(As[kc + q][row]);
                a[mf][1] = __float_as_uint(As[kc + q][row + 8]);
                a[mf][2] = __float_as_uint(As[kc + q + 4][row]);
                a[mf][3] = __float_as_uint(As[kc + q + 4][row + 8]);
            }
#pragma unroll
            for (int nf = 0; nf < 4; nf++) {
                const int col = wn * 32 + nf * 8 + g;
                bv[nf][0] = __float_as_uint(Bs[kc + q][col]);
                bv[nf][1] = __float_as_uint(Bs[kc + q + 4][col]);
            }
#pragma unroll
            for (int mf = 0; mf < 4; mf++)
#pragma unroll
                for (int nf = 0; nf < 4; nf++) mma_tf32(c[mf][nf], a[mf], bv[nf]);
        }
    }

    // store Qt[d][s], tf32-rounded, with head sign
    float* qp = g_Qt + (size_t)b * DD * SS;
#pragma unroll
    for (int mf = 0; mf < 4; mf++) {
        const int r0 = s0 + wm * 64 + mf * 16 + g;
#pragma unroll
        for (int nf = 0; nf < 4; nf++) {
            const int d = d0 + wn * 32 + nf * 8 + 2 * q;
            qp[(size_t)d * SS + r0]           = to_tf32(sign * c[mf][nf][0]);
            qp[(size_t)(d + 1) * SS + r0]     = to_tf32(sign * c[mf][nf][1]);
            qp[(size_t)d * SS + r0 + 8]       = to_tf32(sign * c[mf][nf][2]);
            qp[(size_t)(d + 1) * SS + r0 + 8] = to_tf32(sign * c[mf][nf][3]);
        }
    }
}

// ---------------- K2: Delta GEMM (tf32 mma) + fused sigmoid/weighted reduce --
// Delta[s,t] = sum_d Qt[b][d][s] * Xt[b][d][t]; gpart[b][tb][s] = sum_t w[t]*sigmoid
__global__ __launch_bounds__(256) void k2_attn(const float* __restrict__ W_out) {
    __shared__ float As[16][LDA];   // [k][s] from Qt
    __shared__ float Bs[16][LDA];   // [k][t] from Xt
    __shared__ float red[4][129];   // cross-warp (n-dim) reduction buffer

    const int b  = blockIdx.z;
    const int s0 = blockIdx.x * 128;
    const int t0 = blockIdx.y * 128;
    const int tid = threadIdx.x;
    const int warp = tid >> 5, lane = tid & 31;
    const int wm = warp & 1;
    const int wn = warp >> 1;
    const int g = lane >> 2, q = lane & 3;

    const float* qb = g_Qt + (size_t)b * DD * SS;
    const float* xb = g_Xt + (size_t)b * DD * TT;

    float c[4][4][4];
#pragma unroll
    for (int mf = 0; mf < 4; mf++)
#pragma unroll
        for (int nf = 0; nf < 4; nf++)
#pragma unroll
            for (int r = 0; r < 4; r++) c[mf][nf][r] = 0.f;

    const int lk  = tid >> 5;
    const int ls4 = tid & 31;

    for (int kb = 0; kb < DD; kb += 16) {
        __syncthreads();
#pragma unroll
        for (int r = 0; r < 2; r++) {
            const int k = lk + r * 8;
            *(float4*)&As[k][ls4 * 4] =
                *(const float4*)(qb + (size_t)(kb + k) * SS + s0 + ls4 * 4);
            *(float4*)&Bs[k][ls4 * 4] =
                *(const float4*)(xb + (size_t)(kb + k) * TT + t0 + ls4 * 4);
        }
        __syncthreads();
#pragma unroll
        for (int kc = 0; kc < 16; kc += 8) {
            uint32_t a[4][4], bv[4][2];
#pragma unroll
            for (int mf = 0; mf < 4; mf++) {
                const int row = wm * 64 + mf * 16 + g;
                a[mf][0] = __float_as_uint(As[kc + q][row]);
                a[mf][1] = __float_as_uint(As[kc + q][row + 8]);
                a[mf][2] = __float_as_uint(As[kc + q + 4][row]);
                a[mf][3] = __float_as_uint(As[kc + q + 4][row + 8]);
            }
#pragma unroll
            for (int nf = 0; nf < 4; nf++) {
                const int col = wn * 32 + nf * 8 + g;
                bv[nf][0] = __float_as_uint(Bs[kc + q][col]);
                bv[nf][1] = __float_as_uint(Bs[kc + q + 4][col]);
            }
#pragma unroll
            for (int mf = 0; mf < 4; mf++)
#pragma unroll
                for (int nf = 0; nf < 4; nf++) mma_tf32(c[mf][nf], a[mf], bv[nf]);
        }
    }

    // epilogue: p[mf][r8] = sum over this thread's 8 t-cols of w[t]*sigmoid(delta)
    const float* wrow = W_out + (size_t)(TT - 1) * TT + t0;
    float wv[4][2];
#pragma unroll
    for (int nf = 0; nf < 4; nf++) {
        const int col = wn * 32 + nf * 8 + 2 * q;
        wv[nf][0] = wrow[col];
        wv[nf][1] = wrow[col + 1];
    }
    float p[4][2];
#pragma unroll
    for (int mf = 0; mf < 4; mf++) { p[mf][0] = 0.f; p[mf][1] = 0.f; }
#pragma unroll
    for (int mf = 0; mf < 4; mf++)
#pragma unroll
        for (int nf = 0; nf < 4; nf++) {
            p[mf][0] += wv[nf][0] * sigmoidf_fast(c[mf][nf][0])
                      + wv[nf][1] * sigmoidf_fast(c[mf][nf][1]);
            p[mf][1] += wv[nf][0] * sigmoidf_fast(c[mf][nf][2])
                      + wv[nf][1] * sigmoidf_fast(c[mf][nf][3]);
        }
    // reduce across the 4 lanes of each quad (q dimension)
#pragma unroll
    for (int mf = 0; mf < 4; mf++)
#pragma unroll
        for (int r8 = 0; r8 < 2; r8++) {
            float v = p[mf][r8];
            v += __shfl_xor_sync(0xffffffffu, v, 1);
            v += __shfl_xor_sync(0xffffffffu, v, 2);
            p[mf][r8] = v;
        }
    if (q == 0) {
#pragma unroll
        for (int mf = 0; mf < 4; mf++)
#pragma unroll
            for (int r8 = 0; r8 < 2; r8++)
                red[wn][wm * 64 + mf * 16 + r8 * 8 + g] = p[mf][r8];
    }
    __syncthreads();
    if (tid < 128) {
        const float acc = red[0][tid] + red[1][tid] + red[2][tid] + red[3][tid];
        g_gpart[((size_t)b * 16 + blockIdx.y) * SS + s0 + tid] = acc;
    }
}

// ---------------- K3: g0 = sum over t-tiles ----------------------------------
__global__ void k3_g0() {
    const int idx = blockIdx.x * 256 + threadIdx.x;
    const int b = idx >> 11;
    const float* pz = g_gpart + (size_t)b * 16 * SS + (idx & (SS - 1));
    float acc = 0.f;
#pragma unroll
    for (int tb = 0; tb < 16; tb++) acc += pz[(size_t)tb * SS];
    g_g0[idx] = acc;
}

// ---------------- K4: y0, rowsum (exact fp32 xs) -----------------------------
__global__ void k4_y(const float* __restrict__ xs) {
    const int d = blockIdx.x;
    const int b = blockIdx.y;
    const float* xr = xs + ((size_t)b * DD + d) * TT;
    const float* g = g_g0 + (size_t)b * SS;
    float ay = 0.f, ar = 0.f;
    for (int s = threadIdx.x; s < SVALID; s += 128) {
        const float x = xr[s];
        ay += x * g[s];
        ar += x;
    }
    __shared__ float sy[128], sr[128];
    sy[threadIdx.x] = ay;
    sr[threadIdx.x] = ar;
    __syncthreads();
    for (int st = 64; st > 0; st >>= 1) {
        if (threadIdx.x < st) {
            sy[threadIdx.x] += sy[threadIdx.x + st];
            sr[threadIdx.x] += sr[threadIdx.x + st];
        }
        __syncthreads();
    }
    if (threadIdx.x == 0) {
        g_y[b * DD + d] = sy[0];
        g_r[b * DD + d] = sr[0];
    }
}

// ---------------- K5: final W_PV contraction ---------------------------------
__global__ __launch_bounds__(512) void k5_out(const float* __restrict__ W_PV,
                                              float* __restrict__ out) {
    const int b = blockIdx.x;
    __shared__ float z0[DD], z1[DD];
    const float ws = g_wsum;
    {
        const int d = threadIdx.x;
        const float yv = g_y[b * DD + d];
        const float rv = g_r[b * DD + d];
        z0[d] = yv;
        z1[d] = ws * rv - yv;
    }
    __syncthreads();
    const int warp = threadIdx.x >> 5, lane = threadIdx.x & 31;
    for (int ii = 0; ii < 32; ii++) {
        const int i = warp * 32 + ii;
        const float* z = (i < 256) ? z0 : z1;
        const float* wp = W_PV + (size_t)i * DD;
        float acc = 0.f;
#pragma unroll
        for (int cix = 0; cix < 16; cix++) acc += wp[lane + cix * 32] * z[lane + cix * 32];
#pragma unroll
        for (int off = 16; off > 0; off >>= 1)
            acc += __shfl_down_sync(0xffffffffu, acc, off);
        if (lane == 0) out[b * DD + i] = acc;
    }
}

// ---------------- launch -----------------------------------------------------
extern "C" void kernel_launch(void* const* d_in, const int* in_sizes, int n_in,
                              void* d_out, int out_size) {
    const float* xs    = (const float*)d_in[0];
    const float* W_KQ  = (const float*)d_in[1];
    const float* W_PV  = (const float*)d_in[2];
    const float* W_out = (const float*)d_in[3];
    float* out = (float*)d_out;

    k0_wsum<<<1, 256>>>(W_out);
    k_cvt_xs<<<(BB * DD * TT) / 4 / 256, 256>>>(xs);
    k_cvt_w<<<(DD * DD) / 4 / 256, 256>>>(W_KQ);
    k1_qt<<<dim3(16, 4, BB), 256>>>(nullptr);
    k2_attn<<<dim3(16, 16, BB), 256>>>(W_out);
    k3_g0<<<(BB * SS) / 256, 256>>>();
    k4_y<<<dim3(DD, BB), 128>>>(xs);
    k5_out<<<BB, 512>>>(W_PV, out);
}

// round 9
// speedup vs baseline: 2.7751x; 1.1885x over previous
#include <cuda_runtime.h>
#include <cstdint>

#define BB 16
#define DD 512
#define TT 2048
#define SS 2048      // padded s dimension (valid s < 2047)
#define SVALID 2047
#define LDA 136      // smem row stride (floats): 8-float skew -> conflict-free frag LDS
#define NSTG 3       // cp.async pipeline stages
#define NCHUNK 32    // DD / 16
#define TILE_FLOATS (16 * LDA)                 // one 16-k stage of one operand
#define SMEM_DYN (2 * NSTG * TILE_FLOATS * 4)  // A stages + B stages = 52224 B

// ---------------- scratch (static __device__, no runtime allocation) ---------
__device__ float g_Xt[(size_t)BB * DD * TT];     // tf32-rounded xs
__device__ float g_Wkq[DD * DD];                 // tf32-rounded W_KQ
__device__ float g_Qt[(size_t)BB * DD * SS];     // q-tilde (tf32-rounded), [b][d][s]
__device__ float g_gpart[(size_t)BB * 16 * SS];  // partial g0 per t-tile
__device__ float g_g0[(size_t)BB * SS];
__device__ float g_y[BB * DD];
__device__ float g_r[BB * DD];
__device__ float g_wsum;

// ---------------- helpers ----------------------------------------------------
__device__ __forceinline__ float to_tf32(float x) {
    uint32_t u;
    asm("cvt.rna.tf32.f32 %0, %1;" : "=r"(u) : "f"(x));
    return __uint_as_float(u);
}
__device__ __forceinline__ uint32_t smem_u32(const void* p) {
    uint32_t a;
    asm("{ .reg .u64 t; cvta.to.shared.u64 t, %1; cvt.u32.u64 %0, t; }" : "=r"(a) : "l"(p));
    return a;
}
__device__ __forceinline__ void cp16(uint32_t dst, const float* src) {
    asm volatile("cp.async.cg.shared.global [%0], [%1], 16;" :: "r"(dst), "l"(src) : "memory");
}
__device__ __forceinline__ void mma_tf32(float* c, const uint32_t* a, const uint32_t* b) {
    asm volatile(
        "mma.sync.aligned.m16n8k8.row.col.f32.tf32.tf32.f32 "
        "{%0,%1,%2,%3}, {%4,%5,%6,%7}, {%8,%9}, {%0,%1,%2,%3};"
        : "+f"(c[0]), "+f"(c[1]), "+f"(c[2]), "+f"(c[3])
        : "r"(a[0]), "r"(a[1]), "r"(a[2]), "r"(a[3]), "r"(b[0]), "r"(b[1]));
}
__device__ __forceinline__ float sigmoidf_fast(float x) {
    return 1.f / (1.f + __expf(-x));
}

// ---------------- pipelined GEMM mainloop ------------------------------------
// C(128x128) += A_g(128 rows s/d-major? no: K-major slabs) — operands are
// [k][m]/[k][n] tiles: gmem row k has strideA/strideB floats, 128-wide tile.
// Accumulators: c[mf][nf][4], warp layout 2(m) x 4(n), warp tile 64x32.
__device__ __forceinline__ void gemm_mainloop(
    float c[4][4][4], float* smemf, uint32_t smemb,
    const float* aG, int strideA, const float* bG, int strideB,
    int tid, int wm, int wn, int g, int q)
{
    float* As = smemf;                         // [NSTG][16][LDA]
    float* Bs = smemf + NSTG * TILE_FLOATS;
    const uint32_t aB = smemb;
    const uint32_t bB = smemb + NSTG * TILE_FLOATS * 4;

    // prologue: chunks 0,1
#pragma unroll
    for (int ch = 0; ch < 2; ch++) {
        const float* aGc = aG + (size_t)ch * 16 * strideA;
        const float* bGc = bG + (size_t)ch * 16 * strideB;
        const uint32_t aD = aB + ch * TILE_FLOATS * 4;
        const uint32_t bD = bB + ch * TILE_FLOATS * 4;
#pragma unroll
        for (int h = 0; h < 2; h++) {
            const int idx = tid + h * 256;
            const int row = idx >> 5, cc = idx & 31;
            cp16(aD + (row * LDA + cc * 4) * 4, aGc + (size_t)row * strideA + cc * 4);
            cp16(bD + (row * LDA + cc * 4) * 4, bGc + (size_t)row * strideB + cc * 4);
        }
        asm volatile("cp.async.commit_group;" ::: "memory");
    }

    for (int i = 0; i < NCHUNK; i++) {
        if (i + 1 < NCHUNK) asm volatile("cp.async.wait_group 1;" ::: "memory");
        else                asm volatile("cp.async.wait_group 0;" ::: "memory");
        __syncthreads();

        // prefetch chunk i+2 into slot (i+2)%3  (that slot's compute ended at i-1, pre-sync)
        if (i + 2 < NCHUNK) {
            const int ch = i + 2, sl = ch % NSTG;
            const float* aGc = aG + (size_t)ch * 16 * strideA;
            const float* bGc = bG + (size_t)ch * 16 * strideB;
            const uint32_t aD = aB + sl * TILE_FLOATS * 4;
            const uint32_t bD = bB + sl * TILE_FLOATS * 4;
#pragma unroll
            for (int h = 0; h < 2; h++) {
                const int idx = tid + h * 256;
                const int row = idx >> 5, cc = idx & 31;
                cp16(aD + (row * LDA + cc * 4) * 4, aGc + (size_t)row * strideA + cc * 4);
                cp16(bD + (row * LDA + cc * 4) * 4, bGc + (size_t)row * strideB + cc * 4);
            }
            asm volatile("cp.async.commit_group;" ::: "memory");
        }

        // compute chunk i (slot i%3): two k-sub-steps of 8
        const float* A = As + (i % NSTG) * TILE_FLOATS;
        const float* B = Bs + (i % NSTG) * TILE_FLOATS;
#pragma unroll
        for (int kc = 0; kc < 16; kc += 8) {
            uint32_t a[4][4], bv[4][2];
#pragma unroll
            for (int mf = 0; mf < 4; mf++) {
                const int row = wm * 64 + mf * 16 + g;
                a[mf][0] = __float_as_uint(A[(kc + q) * LDA + row]);
                a[mf][1] = __float_as_uint(A[(kc + q) * LDA + row + 8]);
                a[mf][2] = __float_as_uint(A[(kc + q + 4) * LDA + row]);
                a[mf][3] = __float_as_uint(A[(kc + q + 4) * LDA + row + 8]);
            }
#pragma unroll
            for (int nf = 0; nf < 4; nf++) {
                const int col = wn * 32 + nf * 8 + g;
                bv[nf][0] = __float_as_uint(B[(kc + q) * LDA + col]);
                bv[nf][1] = __float_as_uint(B[(kc + q + 4) * LDA + col]);
            }
#pragma unroll
            for (int mf = 0; mf < 4; mf++)
#pragma unroll
                for (int nf = 0; nf < 4; nf++) mma_tf32(c[mf][nf], a[mf], bv[nf]);
        }
    }
}

// ---------------- K0: Wsum ----------------------------------------------------
__global__ void k0_wsum(const float* __restrict__ W_out) {
    __shared__ float sm[256];
    const float* w = W_out + (size_t)(TT - 1) * TT;
    float acc = 0.f;
    for (int t = threadIdx.x; t < TT; t += 256) acc += w[t];
    sm[threadIdx.x] = acc;
    __syncthreads();
    for (int st = 128; st > 0; st >>= 1) {
        if (threadIdx.x < st) sm[threadIdx.x] += sm[threadIdx.x + st];
        __syncthreads();
    }
    if (threadIdx.x == 0) g_wsum = sm[0];
}

// ---------------- pre-pass: round xs, W_KQ to tf32 ---------------------------
__global__ void k_cvt_xs(const float* __restrict__ xs) {
    const size_t i = (size_t)blockIdx.x * 256 + threadIdx.x;
    float4 v = ((const float4*)xs)[i];
    v.x = to_tf32(v.x); v.y = to_tf32(v.y); v.z = to_tf32(v.z); v.w = to_tf32(v.w);
    ((float4*)g_Xt)[i] = v;
}
__global__ void k_cvt_w(const float* __restrict__ w) {
    const size_t i = (size_t)blockIdx.x * 256 + threadIdx.x;
    float4 v = ((const float4*)w)[i];
    v.x = to_tf32(v.x); v.y = to_tf32(v.y); v.z = to_tf32(v.z); v.w = to_tf32(v.w);
    ((float4*)g_Wkq)[i] = v;
}

// ---------------- K1: Qt[b][d][s] ---------------------------------------------
__global__ __launch_bounds__(256, 2) void k1_qt() {
    extern __shared__ float smemf[];
    const uint32_t smemb = smem_u32(smemf);
    const int b  = blockIdx.z;
    const int s0 = blockIdx.x * 128;
    const int d0 = blockIdx.y * 128;
    const int tid = threadIdx.x;
    const int warp = tid >> 5, lane = tid & 31;
    const int wm = warp & 1, wn = warp >> 1;
    const int g = lane >> 2, q = lane & 3;
    const float sign = (blockIdx.y < 2) ? 1.f : -1.f;

    float c[4][4][4];
#pragma unroll
    for (int mf = 0; mf < 4; mf++)
#pragma unroll
        for (int nf = 0; nf < 4; nf++)
#pragma unroll
            for (int r = 0; r < 4; r++) c[mf][nf][r] = 0.f;

    gemm_mainloop(c, smemf, smemb,
                  g_Xt + (size_t)b * DD * TT + s0, TT,
                  g_Wkq + d0, DD, tid, wm, wn, g, q);

    float* qp = g_Qt + (size_t)b * DD * SS;
#pragma unroll
    for (int mf = 0; mf < 4; mf++) {
        const int r0 = s0 + wm * 64 + mf * 16 + g;
#pragma unroll
        for (int nf = 0; nf < 4; nf++) {
            const int d = d0 + wn * 32 + nf * 8 + 2 * q;
            qp[(size_t)d * SS + r0]           = to_tf32(sign * c[mf][nf][0]);
            qp[(size_t)(d + 1) * SS + r0]     = to_tf32(sign * c[mf][nf][1]);
            qp[(size_t)d * SS + r0 + 8]       = to_tf32(sign * c[mf][nf][2]);
            qp[(size_t)(d + 1) * SS + r0 + 8] = to_tf32(sign * c[mf][nf][3]);
        }
    }
}

// ---------------- K2: Delta GEMM + fused sigmoid/weighted reduce -------------
__global__ __launch_bounds__(256, 2) void k2_attn(const float* __restrict__ W_out) {
    extern __shared__ float smemf[];
    __shared__ float red[4][129];
    const uint32_t smemb = smem_u32(smemf);
    const int b  = blockIdx.z;
    const int s0 = blockIdx.x * 128;
    const int t0 = blockIdx.y * 128;
    const int tid = threadIdx.x;
    const int warp = tid >> 5, lane = tid & 31;
    const int wm = warp & 1, wn = warp >> 1;
    const int g = lane >> 2, q = lane & 3;

    float c[4][4][4];
#pragma unroll
    for (int mf = 0; mf < 4; mf++)
#pragma unroll
        for (int nf = 0; nf < 4; nf++)
#pragma unroll
            for (int r = 0; r < 4; r++) c[mf][nf][r] = 0.f;

    gemm_mainloop(c, smemf, smemb,
                  g_Qt + (size_t)b * DD * SS + s0, SS,
                  g_Xt + (size_t)b * DD * TT + t0, TT, tid, wm, wn, g, q);

    // epilogue: p[mf][r8] = sum over this thread's 8 t-cols of w[t]*sigmoid(delta)
    const float* wrow = W_out + (size_t)(TT - 1) * TT + t0;
    float wv[4][2];
#pragma unroll
    for (int nf = 0; nf < 4; nf++) {
        const int col = wn * 32 + nf * 8 + 2 * q;
        wv[nf][0] = wrow[col];
        wv[nf][1] = wrow[col + 1];
    }
    float p[4][2];
#pragma unroll
    for (int mf = 0; mf < 4; mf++) { p[mf][0] = 0.f; p[mf][1] = 0.f; }
#pragma unroll
    for (int mf = 0; mf < 4; mf++)
#pragma unroll
        for (int nf = 0; nf < 4; nf++) {
            p[mf][0] += wv[nf][0] * sigmoidf_fast(c[mf][nf][0])
                      + wv[nf][1] * sigmoidf_fast(c[mf][nf][1]);
            p[mf][1] += wv[nf][0] * sigmoidf_fast(c[mf][nf][2])
                      + wv[nf][1] * sigmoidf_fast(c[mf][nf][3]);
        }
#pragma unroll
    for (int mf = 0; mf < 4; mf++)
#pragma unroll
        for (int r8 = 0; r8 < 2; r8++) {
            float v = p[mf][r8];
            v += __shfl_xor_sync(0xffffffffu, v, 1);
            v += __shfl_xor_sync(0xffffffffu, v, 2);
            p[mf][r8] = v;
        }
    __syncthreads();   // mainloop's smem no longer needed; reuse barrier for red
    if (q == 0) {
#pragma unroll
        for (int mf = 0; mf < 4; mf++)
#pragma unroll
            for (int r8 = 0; r8 < 2; r8++)
                red[wn][wm * 64 + mf * 16 + r8 * 8 + g] = p[mf][r8];
    }
    __syncthreads();
    if (tid < 128) {
        const float acc = red[0][tid] + red[1][tid] + red[2][tid] + red[3][tid];
        g_gpart[((size_t)b * 16 + blockIdx.y) * SS + s0 + tid] = acc;
    }
}

// ---------------- K3: g0 = sum over t-tiles ----------------------------------
__global__ void k3_g0() {
    const int idx = blockIdx.x * 256 + threadIdx.x;
    const int b = idx >> 11;
    const float* pz = g_gpart + (size_t)b * 16 * SS + (idx & (SS - 1));
    float acc = 0.f;
#pragma unroll
    for (int tb = 0; tb < 16; tb++) acc += pz[(size_t)tb * SS];
    g_g0[idx] = acc;
}

// ---------------- K4: y0, rowsum (exact fp32 xs) -----------------------------
__global__ void k4_y(const float* __restrict__ xs) {
    const int d = blockIdx.x, b = blockIdx.y;
    const float* xr = xs + ((size_t)b * DD + d) * TT;
    const float* g = g_g0 + (size_t)b * SS;
    float ay = 0.f, ar = 0.f;
    for (int s = threadIdx.x; s < SVALID; s += 128) {
        const float x = xr[s];
        ay += x * g[s];
        ar += x;
    }
    __shared__ float sy[128], sr[128];
    sy[threadIdx.x] = ay; sr[threadIdx.x] = ar;
    __syncthreads();
    for (int st = 64; st > 0; st >>= 1) {
        if (threadIdx.x < st) {
            sy[threadIdx.x] += sy[threadIdx.x + st];
            sr[threadIdx.x] += sr[threadIdx.x + st];
        }
        __syncthreads();
    }
    if (threadIdx.x == 0) { g_y[b * DD + d] = sy[0]; g_r[b * DD + d] = sr[0]; }
}

// ---------------- K5: final W_PV contraction ---------------------------------
__global__ __launch_bounds__(512) void k5_out(const float* __restrict__ W_PV,
                                              float* __restrict__ out) {
    const int b = blockIdx.x;
    __shared__ float z0[DD], z1[DD];
    const float ws = g_wsum;
    {
        const int d = threadIdx.x;
        const float yv = g_y[b * DD + d];
        const float rv = g_r[b * DD + d];
        z0[d] = yv;
        z1[d] = ws * rv - yv;
    }
    __syncthreads();
    const int warp = threadIdx.x >> 5, lane = threadIdx.x & 31;
    for (int ii = 0; ii < 32; ii++) {
        const int i = warp * 32 + ii;
        const float* z = (i < 256) ? z0 : z1;
        const float* wp = W_PV + (size_t)i * DD;
        float acc = 0.f;
#pragma unroll
        for (int cix = 0; cix < 16; cix++) acc += wp[lane + cix * 32] * z[lane + cix * 32];
#pragma unroll
        for (int off = 16; off > 0; off >>= 1)
            acc += __shfl_down_sync(0xffffffffu, acc, off);
        if (lane == 0) out[b * DD + i] = acc;
    }
}

// ---------------- launch -----------------------------------------------------
extern "C" void kernel_launch(void* const* d_in, const int* in_sizes, int n_in,
                              void* d_out, int out_size) {
    const float* xs    = (const float*)d_in[0];
    const float* W_KQ  = (const float*)d_in[1];
    const float* W_PV  = (const float*)d_in[2];
    const float* W_out = (const float*)d_in[3];
    float* out = (float*)d_out;

    cudaFuncSetAttribute(k1_qt, cudaFuncAttributeMaxDynamicSharedMemorySize, SMEM_DYN);
    cudaFuncSetAttribute(k2_attn, cudaFuncAttributeMaxDynamicSharedMemorySize, SMEM_DYN);

    k0_wsum<<<1, 256>>>(W_out);
    k_cvt_xs<<<(BB * DD * TT) / 4 / 256, 256>>>(xs);
    k_cvt_w<<<(DD * DD) / 4 / 256, 256>>>(W_KQ);
    k1_qt<<<dim3(16, 4, BB), 256, SMEM_DYN>>>();
    k2_attn<<<dim3(16, 16, BB), 256, SMEM_DYN>>>(W_out);
    k3_g0<<<(BB * SS) / 256, 256>>>();
    k4_y<<<dim3(DD, BB), 128>>>(xs);
    k5_out<<<BB, 512>>>(W_PV, out);
}

// round 11
// speedup vs baseline: 2.8118x; 1.0132x over previous
#include <cuda_runtime.h>
#include <cstdint>

#define BB 16
#define DD 512
#define TT 2048
#define SS 2048      // padded s dimension (valid s < 2047)
#define SVALID 2047
#define LDA 136      // smem row stride (floats): 8-float skew -> conflict-free frag LDS
#define NSTG 3       // cp.async pipeline stages
#define BK 32        // k per chunk
#define NCHUNK 16    // DD / BK
#define TILE_FLOATS (BK * LDA)                 // one 32-k stage of one operand
#define SMEM_DYN (2 * NSTG * TILE_FLOATS * 4)  // A stages + B stages = 104448 B

// ---------------- scratch (static __device__, no runtime allocation) ---------
__device__ float g_Xt[(size_t)BB * DD * TT];     // tf32-rounded xs
__device__ float g_Wkq[DD * DD];                 // tf32-rounded W_KQ
__device__ float g_Qt[(size_t)BB * DD * SS];     // q-tilde (tf32-rounded), [b][d][s]
__device__ float g_gpart[(size_t)BB * 16 * SS];  // partial g0 per t-tile
__device__ float g_g0[(size_t)BB * SS];
__device__ float g_y[BB * DD];
__device__ float g_r[BB * DD];
__device__ float g_wsum;

// ---------------- helpers ----------------------------------------------------
__device__ __forceinline__ float to_tf32(float x) {
    uint32_t u;
    asm("cvt.rna.tf32.f32 %0, %1;" : "=r"(u) : "f"(x));
    return __uint_as_float(u);
}
__device__ __forceinline__ uint32_t smem_u32(const void* p) {
    uint32_t a;
    asm("{ .reg .u64 t; cvta.to.shared.u64 t, %1; cvt.u32.u64 %0, t; }" : "=r"(a) : "l"(p));
    return a;
}
__device__ __forceinline__ void cp16(uint32_t dst, const float* src) {
    asm volatile("cp.async.cg.shared.global [%0], [%1], 16;" :: "r"(dst), "l"(src) : "memory");
}
__device__ __forceinline__ void mma_tf32(float* c, const uint32_t* a, const uint32_t* b) {
    asm volatile(
        "mma.sync.aligned.m16n8k8.row.col.f32.tf32.tf32.f32 "
        "{%0,%1,%2,%3}, {%4,%5,%6,%7}, {%8,%9}, {%0,%1,%2,%3};"
        : "+f"(c[0]), "+f"(c[1]), "+f"(c[2]), "+f"(c[3])
        : "r"(a[0]), "r"(a[1]), "r"(a[2]), "r"(a[3]), "r"(b[0]), "r"(b[1]));
}
__device__ __forceinline__ float sigmoidf_fast(float x) {
    return 1.f / (1.f + __expf(-x));
}

// ---------------- pipelined GEMM mainloop ------------------------------------
// C(128x128) accumulate: operands are [k][m] / [k][n] K-major tiles in gmem
// (row k stride strideA/strideB floats, 128-wide). 3-stage cp.async pipeline,
// BK=32 per chunk => one __syncthreads per 64 HMMAs.
__device__ __forceinline__ void gemm_mainloop(
    float c[4][4][4], float* smemf, uint32_t smemb,
    const float* aG, int strideA, const float* bG, int strideB,
    int tid, int wm, int wn, int g, int q)
{
    float* As = smemf;                         // [NSTG][BK][LDA]
    float* Bs = smemf + NSTG * TILE_FLOATS;
    const uint32_t aB = smemb;
    const uint32_t bB = smemb + NSTG * TILE_FLOATS * 4;

    // prologue: chunks 0,1
#pragma unroll
    for (int ch = 0; ch < 2; ch++) {
        const float* aGc = aG + (size_t)ch * BK * strideA;
        const float* bGc = bG + (size_t)ch * BK * strideB;
        const uint32_t aD = aB + ch * TILE_FLOATS * 4;
        const uint32_t bD = bB + ch * TILE_FLOATS * 4;
#pragma unroll
        for (int h = 0; h < 4; h++) {
            const int idx = tid + h * 256;
            const int row = idx >> 5, cc = idx & 31;
            cp16(aD + (row * LDA + cc * 4) * 4, aGc + (size_t)row * strideA + cc * 4);
            cp16(bD + (row * LDA + cc * 4) * 4, bGc + (size_t)row * strideB + cc * 4);
        }
        asm volatile("cp.async.commit_group;" ::: "memory");
    }

    for (int i = 0; i < NCHUNK; i++) {
        if (i + 1 < NCHUNK) asm volatile("cp.async.wait_group 1;" ::: "memory");
        else                asm volatile("cp.async.wait_group 0;" ::: "memory");
        __syncthreads();

        // prefetch chunk i+2 into slot (i+2)%3 (that slot's compute ended at i-1)
        if (i + 2 < NCHUNK) {
            const int ch = i + 2, sl = ch % NSTG;
            const float* aGc = aG + (size_t)ch * BK * strideA;
            const float* bGc = bG + (size_t)ch * BK * strideB;
            const uint32_t aD = aB + sl * TILE_FLOATS * 4;
            const uint32_t bD = bB + sl * TILE_FLOATS * 4;
#pragma unroll
            for (int h = 0; h < 4; h++) {
                const int idx = tid + h * 256;
                const int row = idx >> 5, cc = idx & 31;
                cp16(aD + (row * LDA + cc * 4) * 4, aGc + (size_t)row * strideA + cc * 4);
                cp16(bD + (row * LDA + cc * 4) * 4, bGc + (size_t)row * strideB + cc * 4);
            }
            asm volatile("cp.async.commit_group;" ::: "memory");
        }

        // compute chunk i (slot i%3): four k-sub-steps of 8 = 64 HMMAs
        const float* A = As + (i % NSTG) * TILE_FLOATS;
        const float* B = Bs + (i % NSTG) * TILE_FLOATS;
#pragma unroll
        for (int kc = 0; kc < BK; kc += 8) {
            uint32_t a[4][4], bv[4][2];
#pragma unroll
            for (int mf = 0; mf < 4; mf++) {
                const int row = wm * 64 + mf * 16 + g;
                a[mf][0] = __float_as_uint(A[(kc + q) * LDA + row]);
                a[mf][1] = __float_as_uint(A[(kc + q) * LDA + row + 8]);
                a[mf][2] = __float_as_uint(A[(kc + q + 4) * LDA + row]);
                a[mf][3] = __float_as_uint(A[(kc + q + 4) * LDA + row + 8]);
            }
#pragma unroll
            for (int nf = 0; nf < 4; nf++) {
                const int col = wn * 32 + nf * 8 + g;
                bv[nf][0] = __float_as_uint(B[(kc + q) * LDA + col]);
                bv[nf][1] = __float_as_uint(B[(kc + q + 4) * LDA + col]);
            }
#pragma unroll
            for (int mf = 0; mf < 4; mf++)
#pragma unroll
                for (int nf = 0; nf < 4; nf++) mma_tf32(c[mf][nf], a[mf], bv[nf]);
        }
    }
}

// ---------------- K0: Wsum ----------------------------------------------------
__global__ void k0_wsum(const float* __restrict__ W_out) {
    __shared__ float sm[256];
    const float* w = W_out + (size_t)(TT - 1) * TT;
    float acc = 0.f;
    for (int t = threadIdx.x; t < TT; t += 256) acc += w[t];
    sm[threadIdx.x] = acc;
    __syncthreads();
    for (int st = 128; st > 0; st >>= 1) {
        if (threadIdx.x < st) sm[threadIdx.x] += sm[threadIdx.x + st];
        __syncthreads();
    }
    if (threadIdx.x == 0) g_wsum = sm[0];
}

// ---------------- pre-pass: round xs, W_KQ to tf32 ---------------------------
__global__ void k_cvt_xs(const float* __restrict__ xs) {
    const size_t i = (size_t)blockIdx.x * 256 + threadIdx.x;
    float4 v = ((const float4*)xs)[i];
    v.x = to_tf32(v.x); v.y = to_tf32(v.y); v.z = to_tf32(v.z); v.w = to_tf32(v.w);
    ((float4*)g_Xt)[i] = v;
}
__global__ void k_cvt_w(const float* __restrict__ w) {
    const size_t i = (size_t)blockIdx.x * 256 + threadIdx.x;
    float4 v = ((const float4*)w)[i];
    v.x = to_tf32(v.x); v.y = to_tf32(v.y); v.z = to_tf32(v.z); v.w = to_tf32(v.w);
    ((float4*)g_Wkq)[i] = v;
}

// ---------------- K1: Qt[b][d][s] ---------------------------------------------
__global__ __launch_bounds__(256, 2) void k1_qt() {
    extern __shared__ float smemf[];
    const uint32_t smemb = smem_u32(smemf);
    const int b  = blockIdx.z;
    const int s0 = blockIdx.x * 128;
    const int d0 = blockIdx.y * 128;
    const int tid = threadIdx.x;
    const int warp = tid >> 5, lane = tid & 31;
    const int wm = warp & 1, wn = warp >> 1;
    const int g = lane >> 2, q = lane & 3;
    const float sign = (blockIdx.y < 2) ? 1.f : -1.f;

    float c[4][4][4];
#pragma unroll
    for (int mf = 0; mf < 4; mf++)
#pragma unroll
        for (int nf = 0; nf < 4; nf++)
#pragma unroll
            for (int r = 0; r < 4; r++) c[mf][nf][r] = 0.f;

    gemm_mainloop(c, smemf, smemb,
                  g_Xt + (size_t)b * DD * TT + s0, TT,
                  g_Wkq + d0, DD, tid, wm, wn, g, q);

    float* qp = g_Qt + (size_t)b * DD * SS;
#pragma unroll
    for (int mf = 0; mf < 4; mf++) {
        const int r0 = s0 + wm * 64 + mf * 16 + g;
#pragma unroll
        for (int nf = 0; nf < 4; nf++) {
            const int d = d0 + wn * 32 + nf * 8 + 2 * q;
            qp[(size_t)d * SS + r0]           = to_tf32(sign * c[mf][nf][0]);
            qp[(size_t)(d + 1) * SS + r0]     = to_tf32(sign * c[mf][nf][1]);
            qp[(size_t)d * SS + r0 + 8]       = to_tf32(sign * c[mf][nf][2]);
            qp[(size_t)(d + 1) * SS + r0 + 8] = to_tf32(sign * c[mf][nf][3]);
        }
    }
}

// ---------------- K2: Delta GEMM + fused sigmoid/weighted reduce -------------
__global__ __launch_bounds__(256, 2) void k2_attn(const float* __restrict__ W_out) {
    extern __shared__ float smemf[];
    __shared__ float red[4][129];
    const uint32_t smemb = smem_u32(smemf);
    const int b  = blockIdx.z;
    const int s0 = blockIdx.x * 128;
    const int t0 = blockIdx.y * 128;
    const int tid = threadIdx.x;
    const int warp = tid >> 5, lane = tid & 31;
    const int wm = warp & 1, wn = warp >> 1;
    const int g = lane >> 2, q = lane & 3;

    float c[4][4][4];
#pragma unroll
    for (int mf = 0; mf < 4; mf++)
#pragma unroll
        for (int nf = 0; nf < 4; nf++)
#pragma unroll
            for (int r = 0; r < 4; r++) c[mf][nf][r] = 0.f;

    gemm_mainloop(c, smemf, smemb,
                  g_Qt + (size_t)b * DD * SS + s0, SS,
                  g_Xt + (size_t)b * DD * TT + t0, TT, tid, wm, wn, g, q);

    // epilogue: p[mf][r8] = sum over this thread's 8 t-cols of w[t]*sigmoid(delta)
    const float* wrow = W_out + (size_t)(TT - 1) * TT + t0;
    float wv[4][2];
#pragma unroll
    for (int nf = 0; nf < 4; nf++) {
        const int col = wn * 32 + nf * 8 + 2 * q;
        wv[nf][0] = wrow[col];
        wv[nf][1] = wrow[col + 1];
    }
    float p[4][2];
#pragma unroll
    for (int mf = 0; mf < 4; mf++) { p[mf][0] = 0.f; p[mf][1] = 0.f; }
#pragma unroll
    for (int mf = 0; mf < 4; mf++)
#pragma unroll
        for (int nf = 0; nf < 4; nf++) {
            p[mf][0] += wv[nf][0] * sigmoidf_fast(c[mf][nf][0])
                      + wv[nf][1] * sigmoidf_fast(c[mf][nf][1]);
            p[mf][1] += wv[nf][0] * sigmoidf_fast(c[mf][nf][2])
                      + wv[nf][1] * sigmoidf_fast(c[mf][nf][3]);
        }
#pragma unroll
    for (int mf = 0; mf < 4; mf++)
#pragma unroll
        for (int r8 = 0; r8 < 2; r8++) {
            float v = p[mf][r8];
            v += __shfl_xor_sync(0xffffffffu, v, 1);
            v += __shfl_xor_sync(0xffffffffu, v, 2);
            p[mf][r8] = v;
        }
    __syncthreads();   // mainloop smem no longer needed; reuse barrier for red
    if (q == 0) {
#pragma unroll
        for (int mf = 0; mf < 4; mf++)
#pragma unroll
            for (int r8 = 0; r8 < 2; r8++)
                red[wn][wm * 64 + mf * 16 + r8 * 8 + g] = p[mf][r8];
    }
    __syncthreads();
    if (tid < 128) {
        const float acc = red[0][tid] + red[1][tid] + red[2][tid] + red[3][tid];
        g_gpart[((size_t)b * 16 + blockIdx.y) * SS + s0 + tid] = acc;
    }
}

// ---------------- K3: g0 = sum over t-tiles ----------------------------------
__global__ void k3_g0() {
    const int idx = blockIdx.x * 256 + threadIdx.x;
    const int b = idx >> 11;
    const float* pz = g_gpart + (size_t)b * 16 * SS + (idx & (SS - 1));
    float acc = 0.f;
#pragma unroll
    for (int tb = 0; tb < 16; tb++) acc += pz[(size_t)tb * SS];
    g_g0[idx] = acc;
}

// ---------------- K4: y0, rowsum (exact fp32 xs) -----------------------------
__global__ void k4_y(const float* __restrict__ xs) {
    const int d = blockIdx.x, b = blockIdx.y;
    const float* xr = xs + ((size_t)b * DD + d) * TT;
    const float* g = g_g0 + (size_t)b * SS;
    float ay = 0.f, ar = 0.f;
    for (int s = threadIdx.x; s < SVALID; s += 128) {
        const float x = xr[s];
        ay += x * g[s];
        ar += x;
    }
    __shared__ float sy[128], sr[128];
    sy[threadIdx.x] = ay; sr[threadIdx.x] = ar;
    __syncthreads();
    for (int st = 64; st > 0; st >>= 1) {
        if (threadIdx.x < st) {
            sy[threadIdx.x] += sy[threadIdx.x + st];
            sr[threadIdx.x] += sr[threadIdx.x + st];
        }
        __syncthreads();
    }
    if (threadIdx.x == 0) { g_y[b * DD + d] = sy[0]; g_r[b * DD + d] = sr[0]; }
}

// ---------------- K5: final W_PV contraction ---------------------------------
__global__ __launch_bounds__(512) void k5_out(const float* __restrict__ W_PV,
                                              float* __restrict__ out) {
    const int b = blockIdx.x;
    __shared__ float z0[DD], z1[DD];
    const float ws = g_wsum;
    {
        const int d = threadIdx.x;
        const float yv = g_y[b * DD + d];
        const float rv = g_r[b * DD + d];
        z0[d] = yv;
        z1[d] = ws * rv - yv;
    }
    __syncthreads();
    const int warp = threadIdx.x >> 5, lane = threadIdx.x & 31;
    for (int ii = 0; ii < 32; ii++) {
        const int i = warp * 32 + ii;
        const float* z = (i < 256) ? z0 : z1;
        const float* wp = W_PV + (size_t)i * DD;
        float acc = 0.f;
#pragma unroll
        for (int cix = 0; cix < 16; cix++) acc += wp[lane + cix * 32] * z[lane + cix * 32];
#pragma unroll
        for (int off = 16; off > 0; off >>= 1)
            acc += __shfl_down_sync(0xffffffffu, acc, off);
        if (lane == 0) out[b * DD + i] = acc;
    }
}

// ---------------- launch -----------------------------------------------------
extern "C" void kernel_launch(void* const* d_in, const int* in_sizes, int n_in,
                              void* d_out, int out_size) {
    const float* xs    = (const float*)d_in[0];
    const float* W_KQ  = (const float*)d_in[1];
    const float* W_PV  = (const float*)d_in[2];
    const float* W_out = (const float*)d_in[3];
    float* out = (float*)d_out;

    cudaFuncSetAttribute(k1_qt, cudaFuncAttributeMaxDynamicSharedMemorySize, SMEM_DYN);
    cudaFuncSetAttribute(k2_attn, cudaFuncAttributeMaxDynamicSharedMemorySize, SMEM_DYN);

    k0_wsum<<<1, 256>>>(W_out);
    k_cvt_xs<<<(BB * DD * TT) / 4 / 256, 256>>>(xs);
    k_cvt_w<<<(DD * DD) / 4 / 256, 256>>>(W_KQ);
    k1_qt<<<dim3(16, 4, BB), 256, SMEM_DYN>>>();
    k2_attn<<<dim3(16, 16, BB), 256, SMEM_DYN>>>(W_out);
    k3_g0<<<(BB * SS) / 256, 256>>>();
    k4_y<<<dim3(DD, BB), 128>>>(xs);
    k5_out<<<BB, 512>>>(W_PV, out);
}